// round 15
// baseline (speedup 1.0000x reference)
#include <cuda_runtime.h>
#include <cuda_fp16.h>
#include <math.h>
#include <stdint.h>

#define NDIM 384
#define C 128
#define NN (NDIM*NDIM)
#define EPS 1e-5f

// Scratch (allocation-free rule: __device__ globals)
__device__ __align__(16) unsigned short g_ah[(size_t)C * NN];
__device__ __align__(16) unsigned short g_bh[(size_t)C * NN];
__device__ __align__(16) unsigned short g_ct[(size_t)C * NN];   // contracted fp16: [c][i][j]
__device__ __align__(16) unsigned short g_gate[(size_t)NN * C]; // sigmoid(gate_o) fp16: [r][c]
// All 6 weights as PAIRED hi-only fragments: [wsel][ks(8)][gp(8)][lane(32)] uint4 =
// (b0,b1 of n-group 2gp, b0,b1 of n-group 2gp+1). Order: Wpa,Wga,Wpb,Wgb,Wgo,Wpo
__device__ uint4 g_wpair[6 * 8 * 8 * 32];

__device__ __forceinline__ float sigmf(float x) { return 1.f / (1.f + __expf(-x)); }

__device__ __forceinline__ uint32_t smem_u32(const void* p) {
    uint32_t a;
    asm("{ .reg .u64 t; cvta.to.shared.u64 t, %1; cvt.u32.u64 %0, t; }" : "=r"(a) : "l"(p));
    return a;
}
__device__ __forceinline__ void ldsm4(uint32_t (&r)[4], uint32_t a) {
    asm volatile("ldmatrix.sync.aligned.m8n8.x4.shared.b16 {%0,%1,%2,%3}, [%4];"
                 : "=r"(r[0]), "=r"(r[1]), "=r"(r[2]), "=r"(r[3]) : "r"(a));
}
__device__ __forceinline__ void ldsm4t(uint32_t (&r)[4], uint32_t a) {
    asm volatile("ldmatrix.sync.aligned.m8n8.x4.trans.shared.b16 {%0,%1,%2,%3}, [%4];"
                 : "=r"(r[0]), "=r"(r[1]), "=r"(r[2]), "=r"(r[3]) : "r"(a));
}
__device__ __forceinline__ void mma16816(float (&c)[4], const uint32_t (&a)[4],
                                         uint32_t b0, uint32_t b1) {
    asm volatile("mma.sync.aligned.m16n8k16.row.col.f32.f16.f16.f32 "
                 "{%0,%1,%2,%3}, {%4,%5,%6,%7}, {%8,%9}, {%0,%1,%2,%3};"
                 : "+f"(c[0]), "+f"(c[1]), "+f"(c[2]), "+f"(c[3])
                 : "r"(a[0]), "r"(a[1]), "r"(a[2]), "r"(a[3]), "r"(b0), "r"(b1));
}
__device__ __forceinline__ void cp16(uint32_t dst, const void* src) {
    asm volatile("cp.async.cg.shared.global [%0], [%1], 16;" :: "r"(dst), "l"(src));
}
#define CP_COMMIT() asm volatile("cp.async.commit_group;" ::: "memory")

__device__ __forceinline__ uint32_t hfbits(float x) {
    __half h = __float2half_rn(x);
    return (uint32_t)*(unsigned short*)&h;
}
__device__ __forceinline__ uint32_t pack2hf(float a, float b) {
    return hfbits(a) | (hfbits(b) << 16);
}

// ===================== k_prep: 6 weights -> paired hi-only fragments =====================
__global__ void __launch_bounds__(256) k_prep(
    const float* __restrict__ W0, const float* __restrict__ W1,
    const float* __restrict__ W2, const float* __restrict__ W3,
    const float* __restrict__ W4, const float* __restrict__ W5)
{
    int gid = blockIdx.x * 256 + threadIdx.x;   // 12288 total
    int lane = gid & 31;
    int gp = (gid >> 5) & 7;
    int ks = (gid >> 8) & 7;
    int wsel = gid >> 11;
    const float* W;
    switch (wsel) {
        case 0: W = W0; break;
        case 1: W = W1; break;
        case 2: W = W2; break;
        case 3: W = W3; break;
        case 4: W = W4; break;
        default: W = W5; break;
    }
    int n0 = gp * 16 + (lane >> 2);
    int n1 = n0 + 8;
    int k0 = ks * 16 + (lane & 3) * 2;
    float a0 = W[n0 * 128 + k0],     a1 = W[n0 * 128 + k0 + 1];
    float a2 = W[n0 * 128 + k0 + 8], a3 = W[n0 * 128 + k0 + 9];
    float b0 = W[n1 * 128 + k0],     b1 = W[n1 * 128 + k0 + 1];
    float b2 = W[n1 * 128 + k0 + 8], b3 = W[n1 * 128 + k0 + 9];
    g_wpair[gid] = make_uint4(pack2hf(a0, a1), pack2hf(a2, a3),
                              pack2hf(b0, b1), pack2hf(b2, b3));
}

// 1-pass gemm, paired weight fragments (LDG.128 feeds two MMAs)
__device__ __forceinline__ void wg_glob1(const uint32_t (&aH)[8][4],
                                         const uint4* __restrict__ Wf, float (&acc)[8][4]) {
#pragma unroll
    for (int t = 0; t < 8; t++)
#pragma unroll
        for (int e = 0; e < 4; e++) acc[t][e] = 0.f;
#pragma unroll 2
    for (int ks = 0; ks < 8; ks++) {
#pragma unroll
        for (int gp = 0; gp < 4; gp++) {
            uint4 f = __ldg(Wf + (ks * 8 + gp) * 32);
            mma16816(acc[2 * gp],     aH[ks], f.x, f.y);
            mma16816(acc[2 * gp + 1], aH[ks], f.z, f.w);
        }
    }
}

// ===================== Stage 2: LN + 5 linears, 512 thr / 128 rows =====================
#define L5_TOT 34816

// combine + scatter to smem (half st[128ch][136r]) + coalesced STG.128
__device__ __forceinline__ void store_hi_staged(
    float (&P)[8][4], float (&G)[8][4],
    const float* __restrict__ bp, const float* __restrict__ bg,
    const float* __restrict__ mask,
    unsigned short* st, unsigned short* __restrict__ gout,
    int r0, int rg, int chalf, int lane, int tid)
{
    int q = lane >> 2, m = lane & 3;
    int rl1 = rg * 16 + q, rl2 = rl1 + 8;
    float m1 = __ldg(mask + r0 + rl1), m2 = __ldg(mask + r0 + rl2);
#pragma unroll
    for (int t = 0; t < 8; t++) {
        int cc = chalf * 64 + t * 8 + 2 * m;
        float p0 = __ldg(bp + cc), p1 = __ldg(bp + cc + 1);
        float g0 = __ldg(bg + cc), g1 = __ldg(bg + cc + 1);
        st[cc * 136 + rl1]       = (unsigned short)hfbits((P[t][0] + p0) * sigmf(G[t][0] + g0) * m1);
        st[(cc + 1) * 136 + rl1] = (unsigned short)hfbits((P[t][1] + p1) * sigmf(G[t][1] + g1) * m1);
        st[cc * 136 + rl2]       = (unsigned short)hfbits((P[t][2] + p0) * sigmf(G[t][2] + g0) * m2);
        st[(cc + 1) * 136 + rl2] = (unsigned short)hfbits((P[t][3] + p1) * sigmf(G[t][3] + g1) * m2);
    }
    __syncthreads();
#pragma unroll
    for (int it = 0; it < 4; it++) {
        int f = tid + it * 512;
        int c = f >> 4, r8 = (f & 15) * 8;
        uint4 v = *(uint4*)&st[c * 136 + r8];
        *(uint4*)(gout + (size_t)c * NN + r0 + r8) = v;
    }
    __syncthreads();
}

__global__ void __launch_bounds__(512, 1) k_lin5(
    const float* __restrict__ z, const float* __restrict__ mask,
    const float* __restrict__ lnw, const float* __restrict__ lnb,
    const float* __restrict__ bpa, const float* __restrict__ bga,
    const float* __restrict__ bpb, const float* __restrict__ bgb,
    const float* __restrict__ bgo)
{
    extern __shared__ char sm[];
    uint32_t sb = smem_u32(sm);
    int tid = threadIdx.x, w = tid >> 5, lane = tid & 31;
    int rg = w & 7, chalf = w >> 3;
    int r0 = blockIdx.x * 128;

    // LayerNorm -> fp16 hi plane (128 rows x 272B)
    {
        float4 wv = ((const float4*)lnw)[lane];
        float4 bv = ((const float4*)lnb)[lane];
#pragma unroll
        for (int rr = 0; rr < 8; rr++) {
            int row = w * 8 + rr;
            float4 v = *(const float4*)(z + (size_t)(r0 + row) * C + lane * 4);
            float s1 = v.x + v.y + v.z + v.w;
            float s2 = v.x * v.x + v.y * v.y + v.z * v.z + v.w * v.w;
#pragma unroll
            for (int o = 16; o; o >>= 1) {
                s1 += __shfl_xor_sync(0xffffffffu, s1, o);
                s2 += __shfl_xor_sync(0xffffffffu, s2, o);
            }
            float mn = s1 * (1.f / 128.f);
            float var = fmaxf(s2 * (1.f / 128.f) - mn * mn, 0.f);
            float rs = rsqrtf(var + EPS);
            v.x = (v.x - mn) * rs * wv.x + bv.x;
            v.y = (v.y - mn) * rs * wv.y + bv.y;
            v.z = (v.z - mn) * rs * wv.z + bv.z;
            v.w = (v.w - mn) * rs * wv.w + bv.w;
            *(uint2*)(sm + row * 272 + lane * 8) =
                make_uint2(pack2hf(v.x, v.y), pack2hf(v.z, v.w));
        }
    }
    __syncthreads();

    uint32_t aoff = (uint32_t)(((rg * 16 + (lane & 15)) * 136 + (lane >> 4) * 8) * 2);

    uint32_t aH[8][4];
#pragma unroll
    for (int ks = 0; ks < 8; ks++) ldsm4(aH[ks], sb + aoff + ks * 32);
    __syncthreads();   // ZH region now dead -> reusable as staging

    const uint4* Wg = g_wpair + (chalf * 4) * 32 + lane;
    unsigned short* st = (unsigned short*)sm;
    float P[8][4], G[8][4];

    // branch a (Wpa=0, Wga=1)
    wg_glob1(aH, Wg + 0 * 2048, P);
    wg_glob1(aH, Wg + 1 * 2048, G);
    store_hi_staged(P, G, bpa, bga, mask, st, g_ah, r0, rg, chalf, lane, tid);

    // branch b (Wpb=2, Wgb=3)
    wg_glob1(aH, Wg + 2 * 2048, P);
    wg_glob1(aH, Wg + 3 * 2048, G);
    store_hi_staged(P, G, bpb, bgb, mask, st, g_bh, r0, rg, chalf, lane, tid);

    // gate_o (Wgo=4) -> stage row-major (half [128][136]) -> coalesced STG.128
    wg_glob1(aH, Wg + 4 * 2048, P);
    {
        int q = lane >> 2, m = lane & 3;
        int rl1 = rg * 16 + q, rl2 = rl1 + 8;
#pragma unroll
        for (int t = 0; t < 8; t++) {
            int cc = chalf * 64 + t * 8 + 2 * m;
            float b0 = __ldg(bgo + cc), b1 = __ldg(bgo + cc + 1);
            *(uint32_t*)(st + rl1 * 136 + cc) = pack2hf(sigmf(P[t][0] + b0), sigmf(P[t][1] + b1));
            *(uint32_t*)(st + rl2 * 136 + cc) = pack2hf(sigmf(P[t][2] + b0), sigmf(P[t][3] + b1));
        }
        __syncthreads();
#pragma unroll
        for (int it = 0; it < 4; it++) {
            int f = tid + it * 512;
            int r = f >> 4, u = (f & 15) * 8;
            uint4 v = *(uint4*)&st[r * 136 + u];
            *(uint4*)(g_gate + (size_t)(r0 + r) * C + u) = v;
        }
    }
}

// ===================== Stage 3: contraction, 64-row chunks, double-buffered ==========
#define CH_BUF 34816
#define CSM_TOT 69632

__global__ void __launch_bounds__(256, 2) k_contract(const float* __restrict__ mask) {
    extern __shared__ char sm[];
    uint32_t sb = smem_u32(sm);
    int tid = threadIdx.x, w = tid >> 5, lane = tid & 31;
    int blk = blockIdx.x;
    int bj = blk % 3, bi = (blk / 3) % 3, ch = blk / 9;
    int ibase = bi * 128, jbase = bj * 128;
    const unsigned short* s0 = g_bh + (size_t)ch * NN + ibase;  // A operand (i-axis)
    const unsigned short* s1 = g_ah + (size_t)ch * NN + jbase;  // B operand (j-axis)
    int ig = w & 3, jg = w >> 2;

    float acc[2][8][4];
#pragma unroll
    for (int r = 0; r < 2; r++)
#pragma unroll
        for (int t = 0; t < 8; t++)
#pragma unroll
            for (int e = 0; e < 4; e++) acc[r][t][e] = 0.f;

    int kl = (lane & 7) + (lane >> 4) * 8;
    int cbit = ((lane >> 3) & 1) * 8;
    uint32_t aoff0 = (uint32_t)((kl * 136 + ig * 32 + cbit) * 2);
    uint32_t aoff1 = aoff0 + 32;
    uint32_t boff = (uint32_t)((kl * 136 + jg * 64 + cbit) * 2);

#define LOAD_CHUNK(k0, bufb) do {                                              \
        _Pragma("unroll")                                                      \
        for (int it = 0; it < 8; it++) {                                       \
            int t2 = tid + it * 256;                                           \
            int p = t2 >> 10, rem = t2 & 1023;                                 \
            int r = rem >> 4, s = rem & 15;                                    \
            const unsigned short* sp = (p == 0) ? s0 : s1;                     \
            cp16((bufb) + p * 17408 + r * 272 + s * 16,                        \
                 sp + (size_t)((k0) + r) * NDIM + s * 8);                      \
        }                                                                      \
        CP_COMMIT();                                                           \
    } while (0)

    LOAD_CHUNK(0,  sb);
    LOAD_CHUNK(64, sb + CH_BUF);

    for (int c = 0; c < 6; c++) {
        if (c < 5) asm volatile("cp.async.wait_group 1;" ::: "memory");
        else       asm volatile("cp.async.wait_group 0;" ::: "memory");
        __syncthreads();
        uint32_t bufb = sb + (c & 1) * CH_BUF;
#pragma unroll
        for (int ks = 0; ks < 4; ks++) {
            uint32_t A0[4], A1[4];
            ldsm4t(A0, bufb + aoff0 + ks * 4352);
            ldsm4t(A1, bufb + aoff1 + ks * 4352);
#pragma unroll
            for (int g = 0; g < 4; g++) {
                uint32_t bH[4];
                ldsm4t(bH, bufb + 17408 + boff + g * 32 + ks * 4352);
                mma16816(acc[0][2 * g],     A0, bH[0], bH[2]);
                mma16816(acc[0][2 * g + 1], A0, bH[1], bH[3]);
                mma16816(acc[1][2 * g],     A1, bH[0], bH[2]);
                mma16816(acc[1][2 * g + 1], A1, bH[1], bH[3]);
            }
        }
        __syncthreads();
        if (c + 2 < 6) LOAD_CHUNK((c + 2) * 64, sb + (c & 1) * CH_BUF);
    }
#undef LOAD_CHUNK

    float* stg = (float*)sm;
    {
        int q = lane >> 2, m = lane & 3;
#pragma unroll
        for (int r = 0; r < 2; r++)
#pragma unroll
            for (int t = 0; t < 8; t++) {
                int row1 = ig * 32 + r * 16 + q, row2 = row1 + 8;
                int col = jg * 64 + (t >> 1) * 16 + (t & 1) * 8 + 2 * m;
                stg[row1 * 132 + col]     = acc[r][t][0];
                stg[row1 * 132 + col + 1] = acc[r][t][1];
                stg[row2 * 132 + col]     = acc[r][t][2];
                stg[row2 * 132 + col + 1] = acc[r][t][3];
            }
    }
    __syncthreads();
#pragma unroll
    for (int it = 0; it < 8; it++) {
        int idx = (tid + it * 256) * 8;
        int row = idx >> 7, col = idx & 127;
        float4 v0 = *(float4*)(stg + row * 132 + col);
        float4 v1 = *(float4*)(stg + row * 132 + col + 4);
        int igl = ibase + row, jgl = jbase + col;
        const float* mrow = mask + (size_t)igl * NDIM + jgl;
        float4 m0 = *(const float4*)mrow;
        float4 m1 = *(const float4*)(mrow + 4);
        uint4 o;
        o.x = pack2hf(v0.x * m0.x, v0.y * m0.y);
        o.y = pack2hf(v0.z * m0.z, v0.w * m0.w);
        o.z = pack2hf(v1.x * m1.x, v1.y * m1.y);
        o.w = pack2hf(v1.z * m1.z, v1.w * m1.w);
        *(uint4*)(g_ct + (size_t)ch * NN + (size_t)igl * NDIM + jgl) = o;
    }
}

// ===================== Stage 4: 512 threads, 128 rows, 1-pass Wpo =====================
#define KO_ZH  34816
#define KO_TOT 69632

__global__ void __launch_bounds__(512, 1) k_out(
    const float* __restrict__ lnw, const float* __restrict__ lnb,
    const float* __restrict__ bo, float* __restrict__ out)
{
    extern __shared__ char sm[];
    uint32_t sb = smem_u32(sm);
    int tid = threadIdx.x, w = tid >> 5, lane = tid & 31;
    int rg = w & 7, chalf = w >> 3;
    int r0 = blockIdx.x * 128;
    uint32_t* stg = (uint32_t*)sm;    // [row][slot] row stride 68 words

    // transposed fp16 load: warp = channel pair, lanes = row quads
#pragma unroll
    for (int it = 0; it < 4; it++) {
        int cpair = w + it * 16;
        const unsigned short* p0 = g_ct + (size_t)(2 * cpair) * NN + r0 + lane * 4;
        uint2 u0 = *(const uint2*)p0;
        uint2 u1 = *(const uint2*)(p0 + NN);
        int r = lane * 4;
        int slot = (cpair + lane) & 63;
        stg[(r + 0) * 68 + slot] = __byte_perm(u0.x, u1.x, 0x5410);
        stg[(r + 1) * 68 + slot] = __byte_perm(u0.x, u1.x, 0x7632);
        stg[(r + 2) * 68 + slot] = __byte_perm(u0.y, u1.y, 0x5410);
        stg[(r + 3) * 68 + slot] = __byte_perm(u0.y, u1.y, 0x7632);
    }
    __syncthreads();

    // LayerNorm: warp handles 8 rows; lane reads slots 2p, 2p+1
    {
        float2 lw0, lb0, lw1, lb1;
        int cp0 = 0, cp1 = 0;
#pragma unroll
        for (int rr = 0; rr < 8; rr++) {
            int row = w * 8 + rr;
            int k = row >> 2;
            if (rr == 0 || rr == 4) {
                cp0 = (2 * lane - k) & 63;
                cp1 = (2 * lane + 1 - k) & 63;
                lw0 = *(const float2*)(lnw + 2 * cp0); lb0 = *(const float2*)(lnb + 2 * cp0);
                lw1 = *(const float2*)(lnw + 2 * cp1); lb1 = *(const float2*)(lnb + 2 * cp1);
            }
            uint2 d = *(uint2*)&stg[row * 68 + 2 * lane];
            __half2 ha = *(__half2*)&d.x;
            __half2 hb = *(__half2*)&d.y;
            float f0 = __low2float(ha), f1 = __high2float(ha);
            float f2 = __low2float(hb), f3 = __high2float(hb);
            float s1 = f0 + f1 + f2 + f3;
            float s2 = f0 * f0 + f1 * f1 + f2 * f2 + f3 * f3;
#pragma unroll
            for (int o = 16; o; o >>= 1) {
                s1 += __shfl_xor_sync(0xffffffffu, s1, o);
                s2 += __shfl_xor_sync(0xffffffffu, s2, o);
            }
            float mn = s1 * (1.f / 128.f);
            float var = fmaxf(s2 * (1.f / 128.f) - mn * mn, 0.f);
            float rs = rsqrtf(var + EPS);
            float n0 = (f0 - mn) * rs * lw0.x + lb0.x;
            float n1 = (f1 - mn) * rs * lw0.y + lb0.y;
            float n2 = (f2 - mn) * rs * lw1.x + lb1.x;
            float n3 = (f3 - mn) * rs * lw1.y + lb1.y;
            *(uint32_t*)(sm + KO_ZH + row * 272 + 4 * cp0) = pack2hf(n0, n1);
            *(uint32_t*)(sm + KO_ZH + row * 272 + 4 * cp1) = pack2hf(n2, n3);
        }
    }
    __syncthreads();

    uint32_t aoff = (uint32_t)(((rg * 16 + (lane & 15)) * 136 + (lane >> 4) * 8) * 2);
    uint32_t aH[8][4];
#pragma unroll
    for (int ks = 0; ks < 8; ks++) ldsm4(aH[ks], sb + KO_ZH + aoff + ks * 32);

    float P[8][4];
    wg_glob1(aH, g_wpair + 5 * 2048 + (chalf * 4) * 32 + lane, P);

    // epilogue: bias + fp16 gate, float2 stores
    {
        int q = lane >> 2, m = lane & 3;
        int r1 = r0 + rg * 16 + q, r2 = r1 + 8;
#pragma unroll
        for (int t = 0; t < 8; t++) {
            int cc = chalf * 64 + t * 8 + 2 * m;
            float b0 = __ldg(bo + cc), b1 = __ldg(bo + cc + 1);
            uint32_t gb1 = *(const uint32_t*)(g_gate + (size_t)r1 * C + cc);
            uint32_t gb2 = *(const uint32_t*)(g_gate + (size_t)r2 * C + cc);
            __half2 gh1 = *(__half2*)&gb1;
            __half2 gh2 = *(__half2*)&gb2;
            float2 o1, o2;
            o1.x = (P[t][0] + b0) * __low2float(gh1);
            o1.y = (P[t][1] + b1) * __high2float(gh1);
            o2.x = (P[t][2] + b0) * __low2float(gh2);
            o2.y = (P[t][3] + b1) * __high2float(gh2);
            *(float2*)(out + (size_t)r1 * C + cc) = o1;
            *(float2*)(out + (size_t)r2 * C + cc) = o2;
        }
    }
}

extern "C" void kernel_launch(void* const* d_in, const int* in_sizes, int n_in,
                              void* d_out, int out_size) {
    const float* z    = (const float*)d_in[0];
    const float* mask = (const float*)d_in[1];
    const float* lniw = (const float*)d_in[2];
    const float* lnib = (const float*)d_in[3];
    const float* lnow = (const float*)d_in[4];
    const float* lnob = (const float*)d_in[5];
    const float* Wpa  = (const float*)d_in[6];
    const float* bpa  = (const float*)d_in[7];
    const float* Wga  = (const float*)d_in[8];
    const float* bga  = (const float*)d_in[9];
    const float* Wpb  = (const float*)d_in[10];
    const float* bpb  = (const float*)d_in[11];
    const float* Wgb  = (const float*)d_in[12];
    const float* bgb  = (const float*)d_in[13];
    const float* Wgo  = (const float*)d_in[14];
    const float* bgo  = (const float*)d_in[15];
    const float* Wpo  = (const float*)d_in[16];
    const float* bpo  = (const float*)d_in[17];
    float* out = (float*)d_out;

    cudaFuncSetAttribute(k_lin5, cudaFuncAttributeMaxDynamicSharedMemorySize, L5_TOT);
    cudaFuncSetAttribute(k_contract, cudaFuncAttributeMaxDynamicSharedMemorySize, CSM_TOT);
    cudaFuncSetAttribute(k_out, cudaFuncAttributeMaxDynamicSharedMemorySize, KO_TOT);

    k_prep<<<48, 256>>>(Wpa, Wga, Wpb, Wgb, Wgo, Wpo);
    k_lin5<<<NN / 128, 512, L5_TOT>>>(z, mask, lniw, lnib, bpa, bga, bpb, bgb, bgo);
    k_contract<<<9 * C, 256, CSM_TOT>>>(mask);
    k_out<<<NN / 128, 512, KO_TOT>>>(lnow, lnob, bpo, out);
}

// round 16
// speedup vs baseline: 1.0354x; 1.0354x over previous
#include <cuda_runtime.h>
#include <cuda_fp16.h>
#include <math.h>
#include <stdint.h>

#define NDIM 384
#define C 128
#define NN (NDIM*NDIM)
#define EPS 1e-5f

// Scratch (allocation-free rule: __device__ globals)
__device__ __align__(16) unsigned short g_ah[(size_t)C * NN];
__device__ __align__(16) unsigned short g_bh[(size_t)C * NN];
__device__ __align__(16) unsigned short g_ct[(size_t)C * NN];   // contracted fp16: [c][i][j]
__device__ __align__(16) unsigned short g_gate[(size_t)NN * C]; // sigmoid(gate_o) fp16: [r][c]
// All 6 weights as PAIRED hi-only fragments: [wsel][ks(8)][gp(8)][lane(32)] uint4 =
// (b0,b1 of n-group 2gp, b0,b1 of n-group 2gp+1). Order: Wpa,Wga,Wpb,Wgb,Wgo,Wpo
__device__ uint4 g_wpair[6 * 8 * 8 * 32];

__device__ __forceinline__ float sigmf(float x) { return 1.f / (1.f + __expf(-x)); }

__device__ __forceinline__ uint32_t smem_u32(const void* p) {
    uint32_t a;
    asm("{ .reg .u64 t; cvta.to.shared.u64 t, %1; cvt.u32.u64 %0, t; }" : "=r"(a) : "l"(p));
    return a;
}
__device__ __forceinline__ void ldsm4(uint32_t (&r)[4], uint32_t a) {
    asm volatile("ldmatrix.sync.aligned.m8n8.x4.shared.b16 {%0,%1,%2,%3}, [%4];"
                 : "=r"(r[0]), "=r"(r[1]), "=r"(r[2]), "=r"(r[3]) : "r"(a));
}
__device__ __forceinline__ void ldsm4t(uint32_t (&r)[4], uint32_t a) {
    asm volatile("ldmatrix.sync.aligned.m8n8.x4.trans.shared.b16 {%0,%1,%2,%3}, [%4];"
                 : "=r"(r[0]), "=r"(r[1]), "=r"(r[2]), "=r"(r[3]) : "r"(a));
}
__device__ __forceinline__ void mma16816(float (&c)[4], const uint32_t (&a)[4],
                                         uint32_t b0, uint32_t b1) {
    asm volatile("mma.sync.aligned.m16n8k16.row.col.f32.f16.f16.f32 "
                 "{%0,%1,%2,%3}, {%4,%5,%6,%7}, {%8,%9}, {%0,%1,%2,%3};"
                 : "+f"(c[0]), "+f"(c[1]), "+f"(c[2]), "+f"(c[3])
                 : "r"(a[0]), "r"(a[1]), "r"(a[2]), "r"(a[3]), "r"(b0), "r"(b1));
}
__device__ __forceinline__ void cp16(uint32_t dst, const void* src) {
    asm volatile("cp.async.cg.shared.global [%0], [%1], 16;" :: "r"(dst), "l"(src));
}
#define CP_COMMIT() asm volatile("cp.async.commit_group;" ::: "memory")

__device__ __forceinline__ uint32_t hfbits(float x) {
    __half h = __float2half_rn(x);
    return (uint32_t)*(unsigned short*)&h;
}
__device__ __forceinline__ uint32_t pack2hf(float a, float b) {
    return hfbits(a) | (hfbits(b) << 16);
}

// ===================== k_prep: 6 weights -> paired hi-only fragments =====================
__global__ void __launch_bounds__(256) k_prep(
    const float* __restrict__ W0, const float* __restrict__ W1,
    const float* __restrict__ W2, const float* __restrict__ W3,
    const float* __restrict__ W4, const float* __restrict__ W5)
{
    int gid = blockIdx.x * 256 + threadIdx.x;   // 12288 total
    int lane = gid & 31;
    int gp = (gid >> 5) & 7;
    int ks = (gid >> 8) & 7;
    int wsel = gid >> 11;
    const float* W;
    switch (wsel) {
        case 0: W = W0; break;
        case 1: W = W1; break;
        case 2: W = W2; break;
        case 3: W = W3; break;
        case 4: W = W4; break;
        default: W = W5; break;
    }
    int n0 = gp * 16 + (lane >> 2);
    int n1 = n0 + 8;
    int k0 = ks * 16 + (lane & 3) * 2;
    float a0 = W[n0 * 128 + k0],     a1 = W[n0 * 128 + k0 + 1];
    float a2 = W[n0 * 128 + k0 + 8], a3 = W[n0 * 128 + k0 + 9];
    float b0 = W[n1 * 128 + k0],     b1 = W[n1 * 128 + k0 + 1];
    float b2 = W[n1 * 128 + k0 + 8], b3 = W[n1 * 128 + k0 + 9];
    g_wpair[gid] = make_uint4(pack2hf(a0, a1), pack2hf(a2, a3),
                              pack2hf(b0, b1), pack2hf(b2, b3));
}

// 1-pass gemm, paired weight fragments (LDG.128 feeds two MMAs)
__device__ __forceinline__ void wg_glob1(const uint32_t (&aH)[8][4],
                                         const uint4* __restrict__ Wf, float (&acc)[8][4]) {
#pragma unroll
    for (int t = 0; t < 8; t++)
#pragma unroll
        for (int e = 0; e < 4; e++) acc[t][e] = 0.f;
#pragma unroll 2
    for (int ks = 0; ks < 8; ks++) {
#pragma unroll
        for (int gp = 0; gp < 4; gp++) {
            uint4 f = __ldg(Wf + (ks * 8 + gp) * 32);
            mma16816(acc[2 * gp],     aH[ks], f.x, f.y);
            mma16816(acc[2 * gp + 1], aH[ks], f.z, f.w);
        }
    }
}

// ===================== Stage 2: LN + 5 linears, 256 thr / 64 rows / 2 CTAs ==========
#define L5_TOT 18432

__device__ __forceinline__ void store_hi_staged(
    float (&P)[8][4], float (&G)[8][4],
    const float* __restrict__ bp, const float* __restrict__ bg,
    const float* __restrict__ mask,
    unsigned short* st, unsigned short* __restrict__ gout,
    int r0, int rg, int chalf, int lane, int tid)
{
    int q = lane >> 2, m = lane & 3;
    int rl1 = rg * 16 + q, rl2 = rl1 + 8;
    float m1 = __ldg(mask + r0 + rl1), m2 = __ldg(mask + r0 + rl2);
#pragma unroll
    for (int t = 0; t < 8; t++) {
        int cc = chalf * 64 + t * 8 + 2 * m;
        float p0 = __ldg(bp + cc), p1 = __ldg(bp + cc + 1);
        float g0 = __ldg(bg + cc), g1 = __ldg(bg + cc + 1);
        st[cc * 72 + rl1]       = (unsigned short)hfbits((P[t][0] + p0) * sigmf(G[t][0] + g0) * m1);
        st[(cc + 1) * 72 + rl1] = (unsigned short)hfbits((P[t][1] + p1) * sigmf(G[t][1] + g1) * m1);
        st[cc * 72 + rl2]       = (unsigned short)hfbits((P[t][2] + p0) * sigmf(G[t][2] + g0) * m2);
        st[(cc + 1) * 72 + rl2] = (unsigned short)hfbits((P[t][3] + p1) * sigmf(G[t][3] + g1) * m2);
    }
    __syncthreads();
#pragma unroll
    for (int it = 0; it < 4; it++) {
        int f = tid + it * 256;
        int c = f >> 3, r8 = (f & 7) * 8;
        uint4 v = *(uint4*)&st[c * 72 + r8];
        *(uint4*)(gout + (size_t)c * NN + r0 + r8) = v;
    }
    __syncthreads();
}

__global__ void __launch_bounds__(256, 2) k_lin5(
    const float* __restrict__ z, const float* __restrict__ mask,
    const float* __restrict__ lnw, const float* __restrict__ lnb,
    const float* __restrict__ bpa, const float* __restrict__ bga,
    const float* __restrict__ bpb, const float* __restrict__ bgb,
    const float* __restrict__ bgo)
{
    extern __shared__ char sm[];
    uint32_t sb = smem_u32(sm);
    int tid = threadIdx.x, w = tid >> 5, lane = tid & 31;
    int rg = w & 3, chalf = w >> 2;
    int r0 = blockIdx.x * 64;

    // LayerNorm -> fp16 hi plane (64 rows x 272B)
    {
        float4 wv = ((const float4*)lnw)[lane];
        float4 bv = ((const float4*)lnb)[lane];
#pragma unroll
        for (int rr = 0; rr < 8; rr++) {
            int row = w * 8 + rr;
            float4 v = *(const float4*)(z + (size_t)(r0 + row) * C + lane * 4);
            float s1 = v.x + v.y + v.z + v.w;
            float s2 = v.x * v.x + v.y * v.y + v.z * v.z + v.w * v.w;
#pragma unroll
            for (int o = 16; o; o >>= 1) {
                s1 += __shfl_xor_sync(0xffffffffu, s1, o);
                s2 += __shfl_xor_sync(0xffffffffu, s2, o);
            }
            float mn = s1 * (1.f / 128.f);
            float var = fmaxf(s2 * (1.f / 128.f) - mn * mn, 0.f);
            float rs = rsqrtf(var + EPS);
            v.x = (v.x - mn) * rs * wv.x + bv.x;
            v.y = (v.y - mn) * rs * wv.y + bv.y;
            v.z = (v.z - mn) * rs * wv.z + bv.z;
            v.w = (v.w - mn) * rs * wv.w + bv.w;
            *(uint2*)(sm + row * 272 + lane * 8) =
                make_uint2(pack2hf(v.x, v.y), pack2hf(v.z, v.w));
        }
    }
    __syncthreads();

    uint32_t aoff = (uint32_t)(((rg * 16 + (lane & 15)) * 136 + (lane >> 4) * 8) * 2);

    uint32_t aH[8][4];
#pragma unroll
    for (int ks = 0; ks < 8; ks++) ldsm4(aH[ks], sb + aoff + ks * 32);
    __syncthreads();   // ZH region now dead -> reusable as staging

    const uint4* Wg = g_wpair + (chalf * 4) * 32 + lane;
    unsigned short* st = (unsigned short*)sm;
    float P[8][4], G[8][4];

    // branch a (Wpa=0, Wga=1)
    wg_glob1(aH, Wg + 0 * 2048, P);
    wg_glob1(aH, Wg + 1 * 2048, G);
    store_hi_staged(P, G, bpa, bga, mask, st, g_ah, r0, rg, chalf, lane, tid);

    // branch b (Wpb=2, Wgb=3)
    wg_glob1(aH, Wg + 2 * 2048, P);
    wg_glob1(aH, Wg + 3 * 2048, G);
    store_hi_staged(P, G, bpb, bgb, mask, st, g_bh, r0, rg, chalf, lane, tid);

    // gate_o (Wgo=4) -> stage row-major -> coalesced STG.128
    wg_glob1(aH, Wg + 4 * 2048, P);
    {
        int q = lane >> 2, m = lane & 3;
        int rl1 = rg * 16 + q, rl2 = rl1 + 8;
#pragma unroll
        for (int t = 0; t < 8; t++) {
            int cc = chalf * 64 + t * 8 + 2 * m;
            float b0 = __ldg(bgo + cc), b1 = __ldg(bgo + cc + 1);
            *(uint32_t*)(st + rl1 * 136 + cc) = pack2hf(sigmf(P[t][0] + b0), sigmf(P[t][1] + b1));
            *(uint32_t*)(st + rl2 * 136 + cc) = pack2hf(sigmf(P[t][2] + b0), sigmf(P[t][3] + b1));
        }
        __syncthreads();
#pragma unroll
        for (int it = 0; it < 4; it++) {
            int f = tid + it * 256;
            int r = f >> 4, u = (f & 15) * 8;
            uint4 v = *(uint4*)&st[r * 136 + u];
            *(uint4*)(g_gate + (size_t)(r0 + r) * C + u) = v;
        }
    }
}

// ===================== Stage 3: contraction, 64-row chunks, double-buffered ==========
#define CH_BUF 34816
#define CSM_TOT 69632

__global__ void __launch_bounds__(256, 2) k_contract(const float* __restrict__ mask) {
    extern __shared__ char sm[];
    uint32_t sb = smem_u32(sm);
    int tid = threadIdx.x, w = tid >> 5, lane = tid & 31;
    int blk = blockIdx.x;
    int bj = blk % 3, bi = (blk / 3) % 3, ch = blk / 9;
    int ibase = bi * 128, jbase = bj * 128;
    const unsigned short* s0 = g_bh + (size_t)ch * NN + ibase;  // A operand (i-axis)
    const unsigned short* s1 = g_ah + (size_t)ch * NN + jbase;  // B operand (j-axis)
    int ig = w & 3, jg = w >> 2;

    float acc[2][8][4];
#pragma unroll
    for (int r = 0; r < 2; r++)
#pragma unroll
        for (int t = 0; t < 8; t++)
#pragma unroll
            for (int e = 0; e < 4; e++) acc[r][t][e] = 0.f;

    int kl = (lane & 7) + (lane >> 4) * 8;
    int cbit = ((lane >> 3) & 1) * 8;
    uint32_t aoff0 = (uint32_t)((kl * 136 + ig * 32 + cbit) * 2);
    uint32_t aoff1 = aoff0 + 32;
    uint32_t boff = (uint32_t)((kl * 136 + jg * 64 + cbit) * 2);

#define LOAD_CHUNK(k0, bufb) do {                                              \
        _Pragma("unroll")                                                      \
        for (int it = 0; it < 8; it++) {                                       \
            int t2 = tid + it * 256;                                           \
            int p = t2 >> 10, rem = t2 & 1023;                                 \
            int r = rem >> 4, s = rem & 15;                                    \
            const unsigned short* sp = (p == 0) ? s0 : s1;                     \
            cp16((bufb) + p * 17408 + r * 272 + s * 16,                        \
                 sp + (size_t)((k0) + r) * NDIM + s * 8);                      \
        }                                                                      \
        CP_COMMIT();                                                           \
    } while (0)

    LOAD_CHUNK(0,  sb);
    LOAD_CHUNK(64, sb + CH_BUF);

    for (int c = 0; c < 6; c++) {
        if (c < 5) asm volatile("cp.async.wait_group 1;" ::: "memory");
        else       asm volatile("cp.async.wait_group 0;" ::: "memory");
        __syncthreads();
        uint32_t bufb = sb + (c & 1) * CH_BUF;
#pragma unroll
        for (int ks = 0; ks < 4; ks++) {
            uint32_t A0[4], A1[4];
            ldsm4t(A0, bufb + aoff0 + ks * 4352);
            ldsm4t(A1, bufb + aoff1 + ks * 4352);
#pragma unroll
            for (int g = 0; g < 4; g++) {
                uint32_t bH[4];
                ldsm4t(bH, bufb + 17408 + boff + g * 32 + ks * 4352);
                mma16816(acc[0][2 * g],     A0, bH[0], bH[2]);
                mma16816(acc[0][2 * g + 1], A0, bH[1], bH[3]);
                mma16816(acc[1][2 * g],     A1, bH[0], bH[2]);
                mma16816(acc[1][2 * g + 1], A1, bH[1], bH[3]);
            }
        }
        __syncthreads();
        if (c + 2 < 6) LOAD_CHUNK((c + 2) * 64, sb + (c & 1) * CH_BUF);
    }
#undef LOAD_CHUNK

    float* stg = (float*)sm;
    {
        int q = lane >> 2, m = lane & 3;
#pragma unroll
        for (int r = 0; r < 2; r++)
#pragma unroll
            for (int t = 0; t < 8; t++) {
                int row1 = ig * 32 + r * 16 + q, row2 = row1 + 8;
                int col = jg * 64 + (t >> 1) * 16 + (t & 1) * 8 + 2 * m;
                stg[row1 * 132 + col]     = acc[r][t][0];
                stg[row1 * 132 + col + 1] = acc[r][t][1];
                stg[row2 * 132 + col]     = acc[r][t][2];
                stg[row2 * 132 + col + 1] = acc[r][t][3];
            }
    }
    __syncthreads();
#pragma unroll
    for (int it = 0; it < 8; it++) {
        int idx = (tid + it * 256) * 8;
        int row = idx >> 7, col = idx & 127;
        float4 v0 = *(float4*)(stg + row * 132 + col);
        float4 v1 = *(float4*)(stg + row * 132 + col + 4);
        int igl = ibase + row, jgl = jbase + col;
        const float* mrow = mask + (size_t)igl * NDIM + jgl;
        float4 m0 = *(const float4*)mrow;
        float4 m1 = *(const float4*)(mrow + 4);
        uint4 o;
        o.x = pack2hf(v0.x * m0.x, v0.y * m0.y);
        o.y = pack2hf(v0.z * m0.z, v0.w * m0.w);
        o.z = pack2hf(v1.x * m1.x, v1.y * m1.y);
        o.w = pack2hf(v1.z * m1.z, v1.w * m1.w);
        *(uint4*)(g_ct + (size_t)ch * NN + (size_t)igl * NDIM + jgl) = o;
    }
}

// ===================== Stage 4: 512 threads, 128 rows, 1-pass Wpo =====================
#define KO_ZH  34816
#define KO_TOT 69632

__global__ void __launch_bounds__(512, 1) k_out(
    const float* __restrict__ lnw, const float* __restrict__ lnb,
    const float* __restrict__ bo, float* __restrict__ out)
{
    extern __shared__ char sm[];
    uint32_t sb = smem_u32(sm);
    int tid = threadIdx.x, w = tid >> 5, lane = tid & 31;
    int rg = w & 7, chalf = w >> 3;
    int r0 = blockIdx.x * 128;
    uint32_t* stg = (uint32_t*)sm;    // [row][slot] row stride 68 words

    // transposed fp16 load: warp = channel pair, lanes = row quads
#pragma unroll
    for (int it = 0; it < 4; it++) {
        int cpair = w + it * 16;
        const unsigned short* p0 = g_ct + (size_t)(2 * cpair) * NN + r0 + lane * 4;
        uint2 u0 = *(const uint2*)p0;
        uint2 u1 = *(const uint2*)(p0 + NN);
        int r = lane * 4;
        int slot = (cpair + lane) & 63;
        stg[(r + 0) * 68 + slot] = __byte_perm(u0.x, u1.x, 0x5410);
        stg[(r + 1) * 68 + slot] = __byte_perm(u0.x, u1.x, 0x7632);
        stg[(r + 2) * 68 + slot] = __byte_perm(u0.y, u1.y, 0x5410);
        stg[(r + 3) * 68 + slot] = __byte_perm(u0.y, u1.y, 0x7632);
    }
    __syncthreads();

    // LayerNorm: warp handles 8 rows; lane reads slots 2p, 2p+1
    {
        float2 lw0, lb0, lw1, lb1;
        int cp0 = 0, cp1 = 0;
#pragma unroll
        for (int rr = 0; rr < 8; rr++) {
            int row = w * 8 + rr;
            int k = row >> 2;
            if (rr == 0 || rr == 4) {
                cp0 = (2 * lane - k) & 63;
                cp1 = (2 * lane + 1 - k) & 63;
                lw0 = *(const float2*)(lnw + 2 * cp0); lb0 = *(const float2*)(lnb + 2 * cp0);
                lw1 = *(const float2*)(lnw + 2 * cp1); lb1 = *(const float2*)(lnb + 2 * cp1);
            }
            uint2 d = *(uint2*)&stg[row * 68 + 2 * lane];
            __half2 ha = *(__half2*)&d.x;
            __half2 hb = *(__half2*)&d.y;
            float f0 = __low2float(ha), f1 = __high2float(ha);
            float f2 = __low2float(hb), f3 = __high2float(hb);
            float s1 = f0 + f1 + f2 + f3;
            float s2 = f0 * f0 + f1 * f1 + f2 * f2 + f3 * f3;
#pragma unroll
            for (int o = 16; o; o >>= 1) {
                s1 += __shfl_xor_sync(0xffffffffu, s1, o);
                s2 += __shfl_xor_sync(0xffffffffu, s2, o);
            }
            float mn = s1 * (1.f / 128.f);
            float var = fmaxf(s2 * (1.f / 128.f) - mn * mn, 0.f);
            float rs = rsqrtf(var + EPS);
            float n0 = (f0 - mn) * rs * lw0.x + lb0.x;
            float n1 = (f1 - mn) * rs * lw0.y + lb0.y;
            float n2 = (f2 - mn) * rs * lw1.x + lb1.x;
            float n3 = (f3 - mn) * rs * lw1.y + lb1.y;
            *(uint32_t*)(sm + KO_ZH + row * 272 + 4 * cp0) = pack2hf(n0, n1);
            *(uint32_t*)(sm + KO_ZH + row * 272 + 4 * cp1) = pack2hf(n2, n3);
        }
    }
    __syncthreads();

    uint32_t aoff = (uint32_t)(((rg * 16 + (lane & 15)) * 136 + (lane >> 4) * 8) * 2);
    uint32_t aH[8][4];
#pragma unroll
    for (int ks = 0; ks < 8; ks++) ldsm4(aH[ks], sb + KO_ZH + aoff + ks * 32);

    float P[8][4];
    wg_glob1(aH, g_wpair + 5 * 2048 + (chalf * 4) * 32 + lane, P);

    // epilogue: bias + fp16 gate, float2 stores
    {
        int q = lane >> 2, m = lane & 3;
        int r1 = r0 + rg * 16 + q, r2 = r1 + 8;
#pragma unroll
        for (int t = 0; t < 8; t++) {
            int cc = chalf * 64 + t * 8 + 2 * m;
            float b0 = __ldg(bo + cc), b1 = __ldg(bo + cc + 1);
            uint32_t gb1 = *(const uint32_t*)(g_gate + (size_t)r1 * C + cc);
            uint32_t gb2 = *(const uint32_t*)(g_gate + (size_t)r2 * C + cc);
            __half2 gh1 = *(__half2*)&gb1;
            __half2 gh2 = *(__half2*)&gb2;
            float2 o1, o2;
            o1.x = (P[t][0] + b0) * __low2float(gh1);
            o1.y = (P[t][1] + b1) * __high2float(gh1);
            o2.x = (P[t][2] + b0) * __low2float(gh2);
            o2.y = (P[t][3] + b1) * __high2float(gh2);
            *(float2*)(out + (size_t)r1 * C + cc) = o1;
            *(float2*)(out + (size_t)r2 * C + cc) = o2;
        }
    }
}

extern "C" void kernel_launch(void* const* d_in, const int* in_sizes, int n_in,
                              void* d_out, int out_size) {
    const float* z    = (const float*)d_in[0];
    const float* mask = (const float*)d_in[1];
    const float* lniw = (const float*)d_in[2];
    const float* lnib = (const float*)d_in[3];
    const float* lnow = (const float*)d_in[4];
    const float* lnob = (const float*)d_in[5];
    const float* Wpa  = (const float*)d_in[6];
    const float* bpa  = (const float*)d_in[7];
    const float* Wga  = (const float*)d_in[8];
    const float* bga  = (const float*)d_in[9];
    const float* Wpb  = (const float*)d_in[10];
    const float* bpb  = (const float*)d_in[11];
    const float* Wgb  = (const float*)d_in[12];
    const float* bgb  = (const float*)d_in[13];
    const float* Wgo  = (const float*)d_in[14];
    const float* bgo  = (const float*)d_in[15];
    const float* Wpo  = (const float*)d_in[16];
    const float* bpo  = (const float*)d_in[17];
    float* out = (float*)d_out;

    cudaFuncSetAttribute(k_contract, cudaFuncAttributeMaxDynamicSharedMemorySize, CSM_TOT);
    cudaFuncSetAttribute(k_out, cudaFuncAttributeMaxDynamicSharedMemorySize, KO_TOT);

    k_prep<<<48, 256>>>(Wpa, Wga, Wpb, Wgb, Wgo, Wpo);
    k_lin5<<<NN / 64, 256, L5_TOT>>>(z, mask, lniw, lnib, bpa, bga, bpb, bgb, bgo);
    k_contract<<<9 * C, 256, CSM_TOT>>>(mask);
    k_out<<<NN / 128, 512, KO_TOT>>>(lnow, lnob, bpo, out);
}

// round 17
// speedup vs baseline: 1.0478x; 1.0120x over previous
#include <cuda_runtime.h>
#include <cuda_fp16.h>
#include <math.h>
#include <stdint.h>

#define NDIM 384
#define C 128
#define NN (NDIM*NDIM)
#define EPS 1e-5f

// Scratch (allocation-free rule: __device__ globals)
__device__ __align__(16) unsigned short g_ah[(size_t)C * NN];
__device__ __align__(16) unsigned short g_bh[(size_t)C * NN];
__device__ __align__(16) unsigned short g_ct[(size_t)C * NN];   // contracted fp16: [c][i][j]
__device__ __align__(16) unsigned short g_gate[(size_t)NN * C]; // sigmoid(gate_o) fp16: [r][c]
// All 6 weights as PAIRED hi-only fragments: [wsel][ks(8)][gp(8)][lane(32)] uint4
__device__ uint4 g_wpair[6 * 8 * 8 * 32];

__device__ __forceinline__ float sigmf(float x) { return 1.f / (1.f + __expf(-x)); }

__device__ __forceinline__ uint32_t smem_u32(const void* p) {
    uint32_t a;
    asm("{ .reg .u64 t; cvta.to.shared.u64 t, %1; cvt.u32.u64 %0, t; }" : "=r"(a) : "l"(p));
    return a;
}
__device__ __forceinline__ void ldsm4(uint32_t (&r)[4], uint32_t a) {
    asm volatile("ldmatrix.sync.aligned.m8n8.x4.shared.b16 {%0,%1,%2,%3}, [%4];"
                 : "=r"(r[0]), "=r"(r[1]), "=r"(r[2]), "=r"(r[3]) : "r"(a));
}
__device__ __forceinline__ void ldsm4t(uint32_t (&r)[4], uint32_t a) {
    asm volatile("ldmatrix.sync.aligned.m8n8.x4.trans.shared.b16 {%0,%1,%2,%3}, [%4];"
                 : "=r"(r[0]), "=r"(r[1]), "=r"(r[2]), "=r"(r[3]) : "r"(a));
}
__device__ __forceinline__ void mma16816(float (&c)[4], const uint32_t (&a)[4],
                                         uint32_t b0, uint32_t b1) {
    asm volatile("mma.sync.aligned.m16n8k16.row.col.f32.f16.f16.f32 "
                 "{%0,%1,%2,%3}, {%4,%5,%6,%7}, {%8,%9}, {%0,%1,%2,%3};"
                 : "+f"(c[0]), "+f"(c[1]), "+f"(c[2]), "+f"(c[3])
                 : "r"(a[0]), "r"(a[1]), "r"(a[2]), "r"(a[3]), "r"(b0), "r"(b1));
}
__device__ __forceinline__ void cp16(uint32_t dst, const void* src) {
    asm volatile("cp.async.cg.shared.global [%0], [%1], 16;" :: "r"(dst), "l"(src));
}
#define CP_COMMIT() asm volatile("cp.async.commit_group;" ::: "memory")

__device__ __forceinline__ uint32_t hfbits(float x) {
    __half h = __float2half_rn(x);
    return (uint32_t)*(unsigned short*)&h;
}
__device__ __forceinline__ uint32_t pack2hf(float a, float b) {
    return hfbits(a) | (hfbits(b) << 16);
}
__device__ __forceinline__ uint32_t hmul2u(uint32_t a, uint32_t b) {
    __half2 r = __hmul2(*(__half2*)&a, *(__half2*)&b);
    return *(uint32_t*)&r;
}

// ===================== k_prep: 6 weights -> paired hi-only fragments =====================
__global__ void __launch_bounds__(256) k_prep(
    const float* __restrict__ W0, const float* __restrict__ W1,
    const float* __restrict__ W2, const float* __restrict__ W3,
    const float* __restrict__ W4, const float* __restrict__ W5)
{
    int gid = blockIdx.x * 256 + threadIdx.x;   // 12288 total
    int lane = gid & 31;
    int gp = (gid >> 5) & 7;
    int ks = (gid >> 8) & 7;
    int wsel = gid >> 11;
    const float* W;
    switch (wsel) {
        case 0: W = W0; break;
        case 1: W = W1; break;
        case 2: W = W2; break;
        case 3: W = W3; break;
        case 4: W = W4; break;
        default: W = W5; break;
    }
    int n0 = gp * 16 + (lane >> 2);
    int n1 = n0 + 8;
    int k0 = ks * 16 + (lane & 3) * 2;
    float a0 = W[n0 * 128 + k0],     a1 = W[n0 * 128 + k0 + 1];
    float a2 = W[n0 * 128 + k0 + 8], a3 = W[n0 * 128 + k0 + 9];
    float b0 = W[n1 * 128 + k0],     b1 = W[n1 * 128 + k0 + 1];
    float b2 = W[n1 * 128 + k0 + 8], b3 = W[n1 * 128 + k0 + 9];
    g_wpair[gid] = make_uint4(pack2hf(a0, a1), pack2hf(a2, a3),
                              pack2hf(b0, b1), pack2hf(b2, b3));
}

// 1-pass gemm, paired weight fragments (LDG.128 feeds two MMAs)
__device__ __forceinline__ void wg_glob1(const uint32_t (&aH)[8][4],
                                         const uint4* __restrict__ Wf, float (&acc)[8][4]) {
#pragma unroll
    for (int t = 0; t < 8; t++)
#pragma unroll
        for (int e = 0; e < 4; e++) acc[t][e] = 0.f;
#pragma unroll 2
    for (int ks = 0; ks < 8; ks++) {
#pragma unroll
        for (int gp = 0; gp < 4; gp++) {
            uint4 f = __ldg(Wf + (ks * 8 + gp) * 32);
            mma16816(acc[2 * gp],     aH[ks], f.x, f.y);
            mma16816(acc[2 * gp + 1], aH[ks], f.z, f.w);
        }
    }
}

// ===================== Stage 2: LN + 5 linears, 256 thr / 64 rows / 2 CTAs ==========
#define L5_TOT 18432

__device__ __forceinline__ void store_hi_staged(
    float (&P)[8][4], float (&G)[8][4],
    const float* __restrict__ bp, const float* __restrict__ bg,
    const float* __restrict__ mask,
    unsigned short* st, unsigned short* __restrict__ gout,
    int r0, int rg, int chalf, int lane, int tid)
{
    int q = lane >> 2, m = lane & 3;
    int rl1 = rg * 16 + q, rl2 = rl1 + 8;
    float m1 = __ldg(mask + r0 + rl1), m2 = __ldg(mask + r0 + rl2);
#pragma unroll
    for (int t = 0; t < 8; t++) {
        int cc = chalf * 64 + t * 8 + 2 * m;
        float p0 = __ldg(bp + cc), p1 = __ldg(bp + cc + 1);
        float g0 = __ldg(bg + cc), g1 = __ldg(bg + cc + 1);
        st[cc * 72 + rl1]       = (unsigned short)hfbits((P[t][0] + p0) * sigmf(G[t][0] + g0) * m1);
        st[(cc + 1) * 72 + rl1] = (unsigned short)hfbits((P[t][1] + p1) * sigmf(G[t][1] + g1) * m1);
        st[cc * 72 + rl2]       = (unsigned short)hfbits((P[t][2] + p0) * sigmf(G[t][2] + g0) * m2);
        st[(cc + 1) * 72 + rl2] = (unsigned short)hfbits((P[t][3] + p1) * sigmf(G[t][3] + g1) * m2);
    }
    __syncthreads();
#pragma unroll
    for (int it = 0; it < 4; it++) {
        int f = tid + it * 256;
        int c = f >> 3, r8 = (f & 7) * 8;
        uint4 v = *(uint4*)&st[c * 72 + r8];
        *(uint4*)(gout + (size_t)c * NN + r0 + r8) = v;
    }
    __syncthreads();
}

__global__ void __launch_bounds__(256, 2) k_lin5(
    const float* __restrict__ z, const float* __restrict__ mask,
    const float* __restrict__ lnw, const float* __restrict__ lnb,
    const float* __restrict__ bpa, const float* __restrict__ bga,
    const float* __restrict__ bpb, const float* __restrict__ bgb,
    const float* __restrict__ bgo)
{
    extern __shared__ char sm[];
    uint32_t sb = smem_u32(sm);
    int tid = threadIdx.x, w = tid >> 5, lane = tid & 31;
    int rg = w & 3, chalf = w >> 2;
    int r0 = blockIdx.x * 64;

    // LayerNorm -> fp16 hi plane (64 rows x 272B)
    {
        float4 wv = ((const float4*)lnw)[lane];
        float4 bv = ((const float4*)lnb)[lane];
#pragma unroll
        for (int rr = 0; rr < 8; rr++) {
            int row = w * 8 + rr;
            float4 v = *(const float4*)(z + (size_t)(r0 + row) * C + lane * 4);
            float s1 = v.x + v.y + v.z + v.w;
            float s2 = v.x * v.x + v.y * v.y + v.z * v.z + v.w * v.w;
#pragma unroll
            for (int o = 16; o; o >>= 1) {
                s1 += __shfl_xor_sync(0xffffffffu, s1, o);
                s2 += __shfl_xor_sync(0xffffffffu, s2, o);
            }
            float mn = s1 * (1.f / 128.f);
            float var = fmaxf(s2 * (1.f / 128.f) - mn * mn, 0.f);
            float rs = rsqrtf(var + EPS);
            v.x = (v.x - mn) * rs * wv.x + bv.x;
            v.y = (v.y - mn) * rs * wv.y + bv.y;
            v.z = (v.z - mn) * rs * wv.z + bv.z;
            v.w = (v.w - mn) * rs * wv.w + bv.w;
            *(uint2*)(sm + row * 272 + lane * 8) =
                make_uint2(pack2hf(v.x, v.y), pack2hf(v.z, v.w));
        }
    }
    __syncthreads();

    uint32_t aoff = (uint32_t)(((rg * 16 + (lane & 15)) * 136 + (lane >> 4) * 8) * 2);

    uint32_t aH[8][4];
#pragma unroll
    for (int ks = 0; ks < 8; ks++) ldsm4(aH[ks], sb + aoff + ks * 32);
    __syncthreads();   // ZH region now dead -> reusable as staging

    const uint4* Wg = g_wpair + (chalf * 4) * 32 + lane;
    unsigned short* st = (unsigned short*)sm;
    float P[8][4], G[8][4];

    // branch a (Wpa=0, Wga=1)
    wg_glob1(aH, Wg + 0 * 2048, P);
    wg_glob1(aH, Wg + 1 * 2048, G);
    store_hi_staged(P, G, bpa, bga, mask, st, g_ah, r0, rg, chalf, lane, tid);

    // branch b (Wpb=2, Wgb=3)
    wg_glob1(aH, Wg + 2 * 2048, P);
    wg_glob1(aH, Wg + 3 * 2048, G);
    store_hi_staged(P, G, bpb, bgb, mask, st, g_bh, r0, rg, chalf, lane, tid);

    // gate_o (Wgo=4) -> stage row-major -> coalesced STG.128
    wg_glob1(aH, Wg + 4 * 2048, P);
    {
        int q = lane >> 2, m = lane & 3;
        int rl1 = rg * 16 + q, rl2 = rl1 + 8;
#pragma unroll
        for (int t = 0; t < 8; t++) {
            int cc = chalf * 64 + t * 8 + 2 * m;
            float b0 = __ldg(bgo + cc), b1 = __ldg(bgo + cc + 1);
            *(uint32_t*)(st + rl1 * 136 + cc) = pack2hf(sigmf(P[t][0] + b0), sigmf(P[t][1] + b1));
            *(uint32_t*)(st + rl2 * 136 + cc) = pack2hf(sigmf(P[t][2] + b0), sigmf(P[t][3] + b1));
        }
        __syncthreads();
#pragma unroll
        for (int it = 0; it < 4; it++) {
            int f = tid + it * 256;
            int r = f >> 4, u = (f & 15) * 8;
            uint4 v = *(uint4*)&st[r * 136 + u];
            *(uint4*)(g_gate + (size_t)(r0 + r) * C + u) = v;
        }
    }
}

// ===================== Stage 3: contraction, 64-row chunks, double-buffered ==========
#define CH_BUF 34816
#define CSM_TOT 69632

__global__ void __launch_bounds__(256, 2) k_contract(const float* __restrict__ mask) {
    extern __shared__ char sm[];
    uint32_t sb = smem_u32(sm);
    int tid = threadIdx.x, w = tid >> 5, lane = tid & 31;
    int blk = blockIdx.x;
    int bj = blk % 3, bi = (blk / 3) % 3, ch = blk / 9;
    int ibase = bi * 128, jbase = bj * 128;
    const unsigned short* s0 = g_bh + (size_t)ch * NN + ibase;  // A operand (i-axis)
    const unsigned short* s1 = g_ah + (size_t)ch * NN + jbase;  // B operand (j-axis)
    int ig = w & 3, jg = w >> 2;

    float acc[2][8][4];
#pragma unroll
    for (int r = 0; r < 2; r++)
#pragma unroll
        for (int t = 0; t < 8; t++)
#pragma unroll
            for (int e = 0; e < 4; e++) acc[r][t][e] = 0.f;

    int kl = (lane & 7) + (lane >> 4) * 8;
    int cbit = ((lane >> 3) & 1) * 8;
    uint32_t aoff0 = (uint32_t)((kl * 136 + ig * 32 + cbit) * 2);
    uint32_t aoff1 = aoff0 + 32;
    uint32_t boff = (uint32_t)((kl * 136 + jg * 64 + cbit) * 2);

#define LOAD_CHUNK(k0, bufb) do {                                              \
        _Pragma("unroll")                                                      \
        for (int it = 0; it < 8; it++) {                                       \
            int t2 = tid + it * 256;                                           \
            int p = t2 >> 10, rem = t2 & 1023;                                 \
            int r = rem >> 4, s = rem & 15;                                    \
            const unsigned short* sp = (p == 0) ? s0 : s1;                     \
            cp16((bufb) + p * 17408 + r * 272 + s * 16,                        \
                 sp + (size_t)((k0) + r) * NDIM + s * 8);                      \
        }                                                                      \
        CP_COMMIT();                                                           \
    } while (0)

    LOAD_CHUNK(0,  sb);
    LOAD_CHUNK(64, sb + CH_BUF);

    for (int c = 0; c < 6; c++) {
        if (c < 5) asm volatile("cp.async.wait_group 1;" ::: "memory");
        else       asm volatile("cp.async.wait_group 0;" ::: "memory");
        __syncthreads();
        uint32_t bufb = sb + (c & 1) * CH_BUF;
#pragma unroll
        for (int ks = 0; ks < 4; ks++) {
            uint32_t A0[4], A1[4];
            ldsm4t(A0, bufb + aoff0 + ks * 4352);
            ldsm4t(A1, bufb + aoff1 + ks * 4352);
#pragma unroll
            for (int g = 0; g < 4; g++) {
                uint32_t bH[4];
                ldsm4t(bH, bufb + 17408 + boff + g * 32 + ks * 4352);
                mma16816(acc[0][2 * g],     A0, bH[0], bH[2]);
                mma16816(acc[0][2 * g + 1], A0, bH[1], bH[3]);
                mma16816(acc[1][2 * g],     A1, bH[0], bH[2]);
                mma16816(acc[1][2 * g + 1], A1, bH[1], bH[3]);
            }
        }
        __syncthreads();
        if (c + 2 < 6) LOAD_CHUNK((c + 2) * 64, sb + (c & 1) * CH_BUF);
    }
#undef LOAD_CHUNK

    // fp16-packed staging: uint32 stgp[128][68], conflict-free (68 mod 32 = 4)
    uint32_t* stgp = (uint32_t*)sm;
    {
        int q = lane >> 2, m = lane & 3;
#pragma unroll
        for (int r = 0; r < 2; r++)
#pragma unroll
            for (int t = 0; t < 8; t++) {
                int row1 = ig * 32 + r * 16 + q, row2 = row1 + 8;
                int colw = jg * 32 + (t >> 1) * 8 + (t & 1) * 4 + m;
                stgp[row1 * 68 + colw] = pack2hf(acc[r][t][0], acc[r][t][1]);
                stgp[row2 * 68 + colw] = pack2hf(acc[r][t][2], acc[r][t][3]);
            }
    }
    __syncthreads();
    // masked fp16 store: 8 cols (uint4) per thread-iter
#pragma unroll
    for (int it = 0; it < 8; it++) {
        int f = tid + it * 256;          // 0..2047
        int row = f >> 4;                // 0..127
        int cw4 = (f & 15) * 4;          // word offset 0..60
        uint4 v = *(uint4*)&stgp[row * 68 + cw4];
        int col = cw4 * 2;               // 0..120
        int igl = ibase + row, jgl = jbase + col;
        const float* mrow = mask + (size_t)igl * NDIM + jgl;
        float4 m0 = *(const float4*)mrow;
        float4 m1 = *(const float4*)(mrow + 4);
        v.x = hmul2u(v.x, pack2hf(m0.x, m0.y));
        v.y = hmul2u(v.y, pack2hf(m0.z, m0.w));
        v.z = hmul2u(v.z, pack2hf(m1.x, m1.y));
        v.w = hmul2u(v.w, pack2hf(m1.z, m1.w));
        *(uint4*)(g_ct + (size_t)ch * NN + (size_t)igl * NDIM + jgl) = v;
    }
}

// ===================== Stage 4: 512 threads, 128 rows, 1-pass Wpo =====================
#define KO_ZH  34816
#define KO_TOT 69632

__global__ void __launch_bounds__(512, 1) k_out(
    const float* __restrict__ lnw, const float* __restrict__ lnb,
    const float* __restrict__ bo, float* __restrict__ out)
{
    extern __shared__ char sm[];
    uint32_t sb = smem_u32(sm);
    int tid = threadIdx.x, w = tid >> 5, lane = tid & 31;
    int rg = w & 7, chalf = w >> 3;
    int r0 = blockIdx.x * 128;
    uint32_t* stg = (uint32_t*)sm;    // [row][slot] row stride 68 words

    // transposed fp16 load: warp = channel pair, lanes = row quads
#pragma unroll
    for (int it = 0; it < 4; it++) {
        int cpair = w + it * 16;
        const unsigned short* p0 = g_ct + (size_t)(2 * cpair) * NN + r0 + lane * 4;
        uint2 u0 = *(const uint2*)p0;
        uint2 u1 = *(const uint2*)(p0 + NN);
        int r = lane * 4;
        int slot = (cpair + lane) & 63;
        stg[(r + 0) * 68 + slot] = __byte_perm(u0.x, u1.x, 0x5410);
        stg[(r + 1) * 68 + slot] = __byte_perm(u0.x, u1.x, 0x7632);
        stg[(r + 2) * 68 + slot] = __byte_perm(u0.y, u1.y, 0x5410);
        stg[(r + 3) * 68 + slot] = __byte_perm(u0.y, u1.y, 0x7632);
    }
    __syncthreads();

    // LayerNorm: warp handles 8 rows; lane reads slots 2p, 2p+1
    {
        float2 lw0, lb0, lw1, lb1;
        int cp0 = 0, cp1 = 0;
#pragma unroll
        for (int rr = 0; rr < 8; rr++) {
            int row = w * 8 + rr;
            int k = row >> 2;
            if (rr == 0 || rr == 4) {
                cp0 = (2 * lane - k) & 63;
                cp1 = (2 * lane + 1 - k) & 63;
                lw0 = *(const float2*)(lnw + 2 * cp0); lb0 = *(const float2*)(lnb + 2 * cp0);
                lw1 = *(const float2*)(lnw + 2 * cp1); lb1 = *(const float2*)(lnb + 2 * cp1);
            }
            uint2 d = *(uint2*)&stg[row * 68 + 2 * lane];
            __half2 ha = *(__half2*)&d.x;
            __half2 hb = *(__half2*)&d.y;
            float f0 = __low2float(ha), f1 = __high2float(ha);
            float f2 = __low2float(hb), f3 = __high2float(hb);
            float s1 = f0 + f1 + f2 + f3;
            float s2 = f0 * f0 + f1 * f1 + f2 * f2 + f3 * f3;
#pragma unroll
            for (int o = 16; o; o >>= 1) {
                s1 += __shfl_xor_sync(0xffffffffu, s1, o);
                s2 += __shfl_xor_sync(0xffffffffu, s2, o);
            }
            float mn = s1 * (1.f / 128.f);
            float var = fmaxf(s2 * (1.f / 128.f) - mn * mn, 0.f);
            float rs = rsqrtf(var + EPS);
            float n0 = (f0 - mn) * rs * lw0.x + lb0.x;
            float n1 = (f1 - mn) * rs * lw0.y + lb0.y;
            float n2 = (f2 - mn) * rs * lw1.x + lb1.x;
            float n3 = (f3 - mn) * rs * lw1.y + lb1.y;
            *(uint32_t*)(sm + KO_ZH + row * 272 + 4 * cp0) = pack2hf(n0, n1);
            *(uint32_t*)(sm + KO_ZH + row * 272 + 4 * cp1) = pack2hf(n2, n3);
        }
    }
    __syncthreads();

    uint32_t aoff = (uint32_t)(((rg * 16 + (lane & 15)) * 136 + (lane >> 4) * 8) * 2);
    uint32_t aH[8][4];
#pragma unroll
    for (int ks = 0; ks < 8; ks++) ldsm4(aH[ks], sb + KO_ZH + aoff + ks * 32);

    float P[8][4];
    wg_glob1(aH, g_wpair + 5 * 2048 + (chalf * 4) * 32 + lane, P);

    // epilogue: bias + fp16 gate, float2 stores
    {
        int q = lane >> 2, m = lane & 3;
        int r1 = r0 + rg * 16 + q, r2 = r1 + 8;
#pragma unroll
        for (int t = 0; t < 8; t++) {
            int cc = chalf * 64 + t * 8 + 2 * m;
            float b0 = __ldg(bo + cc), b1 = __ldg(bo + cc + 1);
            uint32_t gb1 = *(const uint32_t*)(g_gate + (size_t)r1 * C + cc);
            uint32_t gb2 = *(const uint32_t*)(g_gate + (size_t)r2 * C + cc);
            __half2 gh1 = *(__half2*)&gb1;
            __half2 gh2 = *(__half2*)&gb2;
            float2 o1, o2;
            o1.x = (P[t][0] + b0) * __low2float(gh1);
            o1.y = (P[t][1] + b1) * __high2float(gh1);
            o2.x = (P[t][2] + b0) * __low2float(gh2);
            o2.y = (P[t][3] + b1) * __high2float(gh2);
            *(float2*)(out + (size_t)r1 * C + cc) = o1;
            *(float2*)(out + (size_t)r2 * C + cc) = o2;
        }
    }
}

extern "C" void kernel_launch(void* const* d_in, const int* in_sizes, int n_in,
                              void* d_out, int out_size) {
    const float* z    = (const float*)d_in[0];
    const float* mask = (const float*)d_in[1];
    const float* lniw = (const float*)d_in[2];
    const float* lnib = (const float*)d_in[3];
    const float* lnow = (const float*)d_in[4];
    const float* lnob = (const float*)d_in[5];
    const float* Wpa  = (const float*)d_in[6];
    const float* bpa  = (const float*)d_in[7];
    const float* Wga  = (const float*)d_in[8];
    const float* bga  = (const float*)d_in[9];
    const float* Wpb  = (const float*)d_in[10];
    const float* bpb  = (const float*)d_in[11];
    const float* Wgb  = (const float*)d_in[12];
    const float* bgb  = (const float*)d_in[13];
    const float* Wgo  = (const float*)d_in[14];
    const float* bgo  = (const float*)d_in[15];
    const float* Wpo  = (const float*)d_in[16];
    const float* bpo  = (const float*)d_in[17];
    float* out = (float*)d_out;

    cudaFuncSetAttribute(k_contract, cudaFuncAttributeMaxDynamicSharedMemorySize, CSM_TOT);
    cudaFuncSetAttribute(k_out, cudaFuncAttributeMaxDynamicSharedMemorySize, KO_TOT);

    k_prep<<<48, 256>>>(Wpa, Wga, Wpb, Wgb, Wgo, Wpo);
    k_lin5<<<NN / 64, 256, L5_TOT>>>(z, mask, lniw, lnib, bpa, bga, bpb, bgb, bgo);
    k_contract<<<9 * C, 256, CSM_TOT>>>(mask);
    k_out<<<NN / 128, 512, KO_TOT>>>(lnow, lnob, bpo, out);
}